// round 1
// baseline (speedup 1.0000x reference)
#include <cuda_runtime.h>
#include <math.h>

#define SEQ    2048
#define BATCH  2
#define NEMBD  1024
#define NHEAD  16
#define HDIM   64
#define WINDOW 256
#define QSCALE 0.125f          // 1/sqrt(64)
#define MROWS  (BATCH*SEQ)     // 4096
#define MASKV  (-10000.0f)

// Scratch (device globals: allocation-free per harness rules)
__device__ float g_qkv[(size_t)MROWS * 3 * NEMBD];   // [4096, 3072]
__device__ float g_attn[(size_t)MROWS * NEMBD];      // [4096, 1024]

// ---------------------------------------------------------------------------
// Classic register-blocked SGEMM: C[M,N] = A[M,K] @ B[K,N] + bias[N]
// BM=BN=128, BK=16, 256 threads, 8x8 micro-tile per thread.
// ---------------------------------------------------------------------------
template<int M_, int N_, int K_>
__global__ __launch_bounds__(256) void sgemm_bias(const float* __restrict__ A,
                                                  const float* __restrict__ B,
                                                  const float* __restrict__ bias,
                                                  float* __restrict__ C) {
    __shared__ float As[16][132];   // As[k][m], padded
    __shared__ float Bs[16][128];   // Bs[k][n]

    const int m0 = blockIdx.y * 128;
    const int n0 = blockIdx.x * 128;
    const int tid = threadIdx.x;
    const int tx = tid & 15;        // 0..15 -> 8 cols each
    const int ty = tid >> 4;        // 0..15 -> 8 rows each

    float acc[8][8];
#pragma unroll
    for (int i = 0; i < 8; i++)
#pragma unroll
        for (int j = 0; j < 8; j++) acc[i][j] = 0.f;

    for (int k0 = 0; k0 < K_; k0 += 16) {
        // A tile: 128x16 -> As[k][m]  (512 float4 loads)
#pragma unroll
        for (int it = 0; it < 2; it++) {
            int i  = tid + it * 256;
            int m  = i >> 2;
            int k4 = (i & 3) * 4;
            float4 v = *(const float4*)(A + (size_t)(m0 + m) * K_ + k0 + k4);
            As[k4 + 0][m] = v.x;
            As[k4 + 1][m] = v.y;
            As[k4 + 2][m] = v.z;
            As[k4 + 3][m] = v.w;
        }
        // B tile: 16x128 -> Bs[k][n]  (fully coalesced)
#pragma unroll
        for (int it = 0; it < 2; it++) {
            int i  = tid + it * 256;
            int k  = i >> 5;
            int n4 = (i & 31) * 4;
            *(float4*)&Bs[k][n4] = *(const float4*)(B + (size_t)(k0 + k) * N_ + n0 + n4);
        }
        __syncthreads();

#pragma unroll
        for (int k = 0; k < 16; k++) {
            float a[8], b[8];
            *(float4*)&a[0] = *(float4*)&As[k][ty * 8];
            *(float4*)&a[4] = *(float4*)&As[k][ty * 8 + 4];
            *(float4*)&b[0] = *(float4*)&Bs[k][tx * 8];
            *(float4*)&b[4] = *(float4*)&Bs[k][tx * 8 + 4];
#pragma unroll
            for (int i = 0; i < 8; i++)
#pragma unroll
                for (int j = 0; j < 8; j++) acc[i][j] += a[i] * b[j];
        }
        __syncthreads();
    }

    // epilogue: + bias, write C
#pragma unroll
    for (int i = 0; i < 8; i++) {
        const int m = m0 + ty * 8 + i;
#pragma unroll
        for (int j4 = 0; j4 < 2; j4++) {
            const int n = n0 + tx * 8 + j4 * 4;
            float4 v;
            v.x = acc[i][j4 * 4 + 0] + bias[n + 0];
            v.y = acc[i][j4 * 4 + 1] + bias[n + 1];
            v.z = acc[i][j4 * 4 + 2] + bias[n + 2];
            v.w = acc[i][j4 * 4 + 3] + bias[n + 3];
            *(float4*)(C + (size_t)m * N_ + n) = v;
        }
    }
}

// ---------------------------------------------------------------------------
// Sliding-window causal flash attention.
// One block per (64-query tile, head, batch). 256 threads = 16x16,
// 4x4 micro-tile on the 64x64 score tile. Online softmax.
// qkv layout: [B*T, 3072], q at col h*64, k at 1024+h*64, v at 2048+h*64.
// ---------------------------------------------------------------------------
__global__ __launch_bounds__(256) void attn_kernel(const float* __restrict__ qkv,
                                                   float* __restrict__ out) {
    extern __shared__ float sm[];
    float(*Qs)[68] = (float(*)[68])(sm);              // Qs[d][m] (transposed)
    float(*Ks)[68] = (float(*)[68])(sm + 64 * 68);    // Ks[d][n] (transposed)
    float(*Vs)[68] = (float(*)[68])(sm + 2 * 64 * 68);// Vs[n][d] (natural)
    float(*Ps)[68] = (float(*)[68])(sm + 3 * 64 * 68);// Ps[m][n] (natural)

    const int q0 = blockIdx.x * 64;
    const int h  = blockIdx.y;
    const int b  = blockIdx.z;
    const int tid = threadIdx.x;
    const int tx = tid & 15;   // score cols n = 4*tx..; O cols d = 4*tx..
    const int ty = tid >> 4;   // score rows m = 4*ty..

    const float* qb = qkv + (size_t)b * SEQ * 3072 + h * 64;
    const float* kb = qb + 1024;
    const float* vb = qb + 2048;

    // Load Q tile (64x64) transposed into Qs[d][m]
#pragma unroll
    for (int it = 0; it < 4; it++) {
        int i  = tid + it * 256;
        int m  = i >> 4;
        int d4 = (i & 15) * 4;
        float4 v = *(const float4*)(qb + (size_t)(q0 + m) * 3072 + d4);
        Qs[d4 + 0][m] = v.x;
        Qs[d4 + 1][m] = v.y;
        Qs[d4 + 2][m] = v.z;
        Qs[d4 + 3][m] = v.w;
    }

    float acc[4][4];
#pragma unroll
    for (int i = 0; i < 4; i++)
#pragma unroll
        for (int j = 0; j < 4; j++) acc[i][j] = 0.f;
    float mrow[4], lrow[4];
#pragma unroll
    for (int i = 0; i < 4; i++) { mrow[i] = -1e30f; lrow[i] = 0.f; }

    int jlo = q0 - (WINDOW - 1);
    if (jlo < 0) jlo = 0;
    const int kt_first = (jlo / 64) * 64;
    const int kt_last  = q0;   // tiles kt_first .. q0 inclusive (step 64)

    for (int kt = kt_first; kt <= kt_last + 63; kt += 64) {
        __syncthreads();   // previous tile's Ks/Vs/Ps fully consumed

        // Load K (transposed) and V (natural) tiles
#pragma unroll
        for (int it = 0; it < 4; it++) {
            int i  = tid + it * 256;
            int n  = i >> 4;
            int d4 = (i & 15) * 4;
            float4 kv = *(const float4*)(kb + (size_t)(kt + n) * 3072 + d4);
            Ks[d4 + 0][n] = kv.x;
            Ks[d4 + 1][n] = kv.y;
            Ks[d4 + 2][n] = kv.z;
            Ks[d4 + 3][n] = kv.w;
            *(float4*)&Vs[n][d4] = *(const float4*)(vb + (size_t)(kt + n) * 3072 + d4);
        }
        __syncthreads();

        // S = Q @ K^T  (4x4 micro-tile)
        float s[4][4];
#pragma unroll
        for (int i = 0; i < 4; i++)
#pragma unroll
            for (int j = 0; j < 4; j++) s[i][j] = 0.f;

#pragma unroll 16
        for (int d = 0; d < 64; d++) {
            float a[4], kk[4];
            *(float4*)a  = *(float4*)&Qs[d][ty * 4];
            *(float4*)kk = *(float4*)&Ks[d][tx * 4];
#pragma unroll
            for (int i = 0; i < 4; i++)
#pragma unroll
                for (int j = 0; j < 4; j++) s[i][j] += a[i] * kk[j];
        }

        // scale + sliding-window causal mask (matches reference: masked = -10000,
        // exp underflows to exactly 0 in fp32)
#pragma unroll
        for (int i = 0; i < 4; i++) {
            const int gi = q0 + ty * 4 + i;
#pragma unroll
            for (int j = 0; j < 4; j++) {
                const int gj = kt + tx * 4 + j;
                const bool ok = (gj <= gi) && (gj > gi - WINDOW);
                s[i][j] = ok ? s[i][j] * QSCALE : MASKV;
            }
        }

        // online softmax per row (reduce over the 16 tx lanes)
#pragma unroll
        for (int i = 0; i < 4; i++) {
            float tmax = fmaxf(fmaxf(s[i][0], s[i][1]), fmaxf(s[i][2], s[i][3]));
#pragma unroll
            for (int o = 1; o < 16; o <<= 1)
                tmax = fmaxf(tmax, __shfl_xor_sync(0xffffffffu, tmax, o));
            const float mnew = fmaxf(mrow[i], tmax);
            const float corr = __expf(mrow[i] - mnew);
            mrow[i] = mnew;
            float rs = 0.f;
#pragma unroll
            for (int j = 0; j < 4; j++) {
                const float p = __expf(s[i][j] - mnew);
                s[i][j] = p;
                rs += p;
            }
#pragma unroll
            for (int o = 1; o < 16; o <<= 1)
                rs += __shfl_xor_sync(0xffffffffu, rs, o);
            lrow[i] = lrow[i] * corr + rs;
#pragma unroll
            for (int j = 0; j < 4; j++) acc[i][j] *= corr;
        }

        // stage P (natural layout, conflict-free float4 stores)
#pragma unroll
        for (int i = 0; i < 4; i++) {
            float4 pv = make_float4(s[i][0], s[i][1], s[i][2], s[i][3]);
            *(float4*)&Ps[ty * 4 + i][tx * 4] = pv;
        }
        __syncthreads();

        // O += P @ V
#pragma unroll 16
        for (int n = 0; n < 64; n++) {
            const float a0 = Ps[ty * 4 + 0][n];
            const float a1 = Ps[ty * 4 + 1][n];
            const float a2 = Ps[ty * 4 + 2][n];
            const float a3 = Ps[ty * 4 + 3][n];
            float v[4];
            *(float4*)v = *(float4*)&Vs[n][tx * 4];
#pragma unroll
            for (int j = 0; j < 4; j++) {
                acc[0][j] += a0 * v[j];
                acc[1][j] += a1 * v[j];
                acc[2][j] += a2 * v[j];
                acc[3][j] += a3 * v[j];
            }
        }
    }

    // finalize + write: out[b*T + t][h*64 + d]
#pragma unroll
    for (int i = 0; i < 4; i++) {
        const float inv = 1.0f / lrow[i];
        float4 v;
        v.x = acc[i][0] * inv;
        v.y = acc[i][1] * inv;
        v.z = acc[i][2] * inv;
        v.w = acc[i][3] * inv;
        *(float4*)(out + (size_t)(b * SEQ + q0 + ty * 4 + i) * NEMBD + h * 64 + tx * 4) = v;
    }
}

// ---------------------------------------------------------------------------

static const size_t ATTN_SMEM = 4 * 64 * 68 * sizeof(float);  // 69632 B

extern "C" void kernel_launch(void* const* d_in, const int* in_sizes, int n_in,
                              void* d_out, int out_size) {
    const float* x      = (const float*)d_in[0];   // [2,2048,1024]
    const float* w_attn = (const float*)d_in[1];   // [1024,3072]
    const float* b_attn = (const float*)d_in[2];   // [3072]
    const float* w_proj = (const float*)d_in[3];   // [1024,1024]
    const float* b_proj = (const float*)d_in[4];   // [1024]
    float* out = (float*)d_out;                    // [2,2048,1024]

    float* qkv;  cudaGetSymbolAddress((void**)&qkv,  g_qkv);
    float* attn; cudaGetSymbolAddress((void**)&attn, g_attn);

    cudaFuncSetAttribute(attn_kernel, cudaFuncAttributeMaxDynamicSharedMemorySize,
                         (int)ATTN_SMEM);

    // 1) QKV projection: [4096,1024] @ [1024,3072] + b_attn
    sgemm_bias<MROWS, 3 * NEMBD, NEMBD><<<dim3(3 * NEMBD / 128, MROWS / 128), 256>>>(
        x, w_attn, b_attn, qkv);

    // 2) sliding-window attention -> g_attn [4096,1024]
    attn_kernel<<<dim3(SEQ / 64, NHEAD, BATCH), 256, ATTN_SMEM>>>(qkv, attn);

    // 3) output projection: [4096,1024] @ [1024,1024] + b_proj
    sgemm_bias<MROWS, NEMBD, NEMBD><<<dim3(NEMBD / 128, MROWS / 128), 256>>>(
        attn, w_proj, b_proj, out);
}